// round 5
// baseline (speedup 1.0000x reference)
#include <cuda_runtime.h>
#include <cstdint>

#define NROWS   131072
#define DIMS    32
#define NC      512
#define NC2     256
#define NBLK    148
#define NTH     256
#define NWARPS  8
#define ROWBLKS 4096

typedef unsigned long long u64;
typedef unsigned int       u32;

// smem layout (bytes):
//   [0      , 65536) : centers row-major float[512][32]
//   [65536  , 69632) : coef float4 scoef[c2] = {a0, a1, b0, b1}
//   [69632  , 71680) : float2 sg[c2] = {g0, g1}
//   [71680  , 77824) : float2 sw[c2*3+k]
#define SMEM_COEF 65536
#define SMEM_G    (65536 + 4096)
#define SMEM_W    (65536 + 4096 + 2048)
#define SMEM_BYTES (65536 + 4096 + 2048 + 6144)

#define FMA2(acc, a, b) \
    asm("fma.rn.f32x2 %0, %1, %2, %0;" : "+l"(acc) : "l"(a), "l"(b))

__device__ __forceinline__ u64 dup2(float v) {
    u64 r; u32 u = __float_as_uint(v);
    asm("mov.b64 %0, {%1, %1};" : "=l"(r) : "r"(u));
    return r;
}
__device__ __forceinline__ u64 pack2(u32 a, u32 b) {
    u64 r; asm("mov.b64 %0, {%1, %2};" : "=l"(r) : "r"(a), "r"(b));
    return r;
}
__device__ __forceinline__ void unpack2(u64 v, u32& a, u32& b) {
    asm("mov.b64 {%0, %1}, %2;" : "=r"(a), "=r"(b) : "l"(v));
}

// Process R rows against all 512 centers, software-pipelined one center ahead.
template<int R>
__device__ __forceinline__ void process_rows(
    const float* __restrict__ X, float* __restrict__ O,
    const int* rows, const unsigned char* smem_raw,
    float bo0, float bo1, float bo2)
{
    const ulonglong2* sc    = (const ulonglong2*)(smem_raw);             // 8 per center
    const ulonglong2* scoef = (const ulonglong2*)(smem_raw + SMEM_COEF); // {a0,a1},{b0,b1}
    const u64*        sg    = (const u64*)(smem_raw + SMEM_G);
    const u64*        sw    = (const u64*)(smem_raw + SMEM_W);

    // x rows as packed dim-pairs + dup'd ||x||^2
    u64 xp[R][16];
    u64 xsqd[R];
    #pragma unroll
    for (int r = 0; r < R; ++r) {
        const ulonglong2* xr = (const ulonglong2*)(X + (size_t)rows[r] * DIMS);
        u64 sq = 0ull;
        #pragma unroll
        for (int q = 0; q < 8; ++q) {
            ulonglong2 v = xr[q];
            xp[r][2 * q]     = v.x;
            xp[r][2 * q + 1] = v.y;
            FMA2(sq, v.x, v.x);
            FMA2(sq, v.y, v.y);
        }
        u32 lo, hi; unpack2(sq, lo, hi);
        xsqd[r] = dup2(__uint_as_float(lo) + __uint_as_float(hi));
    }

    u64 op[3][R];
    #pragma unroll
    for (int k = 0; k < 3; ++k)
        #pragma unroll
        for (int r = 0; r < R; ++r) op[k][r] = 0ull;

    // double-buffered center registers (one center = 8 x 16B)
    ulonglong2 bufA[8], bufB[8];
    #pragma unroll
    for (int i = 0; i < 8; ++i) bufA[i] = sc[i];   // preload center 0

    const ulonglong2* pc = sc + 8;                 // next center to fetch

    #pragma unroll 1
    for (int c2 = 0; c2 < NC2; ++c2) {
        u64 acc0[R], acc1[R];
        #pragma unroll
        for (int r = 0; r < R; ++r) { acc0[r] = 0ull; acc1[r] = 0ull; }

        // prefetch odd center (2*c2+1) into B, consume A (center 2*c2)
        #pragma unroll
        for (int i = 0; i < 8; ++i) bufB[i] = pc[i];
        pc += 8;
        #pragma unroll
        for (int d8 = 0; d8 < 8; ++d8) {
            #pragma unroll
            for (int r = 0; r < R; ++r) {
                FMA2(acc0[r], xp[r][2 * d8],     bufA[d8].x);
                FMA2(acc0[r], xp[r][2 * d8 + 1], bufA[d8].y);
            }
        }

        // prefetch even center (2*c2+2) into A (last iter reads coef region:
        // in-bounds of dynamic smem, data unused), consume B
        #pragma unroll
        for (int i = 0; i < 8; ++i) bufA[i] = pc[i];
        pc += 8;
        #pragma unroll
        for (int d8 = 0; d8 < 8; ++d8) {
            #pragma unroll
            for (int r = 0; r < R; ++r) {
                FMA2(acc1[r], xp[r][2 * d8],     bufB[d8].x);
                FMA2(acc1[r], xp[r][2 * d8 + 1], bufB[d8].y);
            }
        }

        // epilogue for center pair c2 (centers 2c2, 2c2+1), packed over centers
        ulonglong2 ab = scoef[c2];
        u64 g  = sg[c2];
        u64 w0 = sw[c2 * 3 + 0], w1 = sw[c2 * 3 + 1], w2 = sw[c2 * 3 + 2];
        #pragma unroll
        for (int r = 0; r < R; ++r) {
            u32 aLo, aHi, bLo, bHi;
            unpack2(acc0[r], aLo, aHi);
            unpack2(acc1[r], bLo, bHi);
            u64 pe = pack2(aLo, bLo);   // even-dim partials of both centers
            u64 po = pack2(aHi, bHi);   // odd-dim partials
            u64 t;
            // t = a*xsq + b + g*(pe+po)  ==  -0.5*log2e*dist2/sigma^2
            asm("fma.rn.f32x2 %0, %1, %2, %3;" : "=l"(t)
                : "l"(ab.x), "l"(xsqd[r]), "l"(ab.y));
            FMA2(t, g, pe);
            FMA2(t, g, po);
            u32 t0, t1; unpack2(t, t0, t1);
            float e0, e1;
            asm("ex2.approx.ftz.f32 %0, %1;" : "=f"(e0) : "f"(__uint_as_float(t0)));
            asm("ex2.approx.ftz.f32 %0, %1;" : "=f"(e1) : "f"(__uint_as_float(t1)));
            u64 rp = pack2(__float_as_uint(e0), __float_as_uint(e1)), h;
            // h = (2^(t/2))^2 : subnormal-correct via non-ftz packed mul
            asm("mul.rn.f32x2 %0, %1, %2;" : "=l"(h) : "l"(rp), "l"(rp));
            FMA2(op[0][r], h, w0);
            FMA2(op[1][r], h, w1);
            FMA2(op[2][r], h, w2);
        }
    }

    #pragma unroll
    for (int r = 0; r < R; ++r) {
        float* Or = O + (size_t)rows[r] * 3;
        u32 lo, hi;
        unpack2(op[0][r], lo, hi);
        Or[0] = __uint_as_float(lo) + __uint_as_float(hi) + bo0;
        unpack2(op[1][r], lo, hi);
        Or[1] = __uint_as_float(lo) + __uint_as_float(hi) + bo1;
        unpack2(op[2][r], lo, hi);
        Or[2] = __uint_as_float(lo) + __uint_as_float(hi) + bo2;
    }
}

__global__ void __launch_bounds__(NTH, 1)
rbfn_kernel(const float* __restrict__ X,    // [N, D]
            const float* __restrict__ Cn,   // [C, D]
            const float* __restrict__ Sg,   // [1, C]
            const float* __restrict__ Wp,   // [DO, C]
            const float* __restrict__ Bp,   // [DO]
            float* __restrict__ O)          // [N, 3]
{
    extern __shared__ unsigned char smem_raw[];
    const int tid = threadIdx.x;

    // stage centers row-major (straight float4 copy)
    {
        float4*       dst = (float4*)smem_raw;
        const float4* src = (const float4*)Cn;
        #pragma unroll
        for (int i = tid; i < NC * DIMS / 4; i += NTH) dst[i] = src[i];
    }
    // folded coefficient tables (one thread per center-pair)
    for (int c2 = tid; c2 < NC2; c2 += NTH) {
        float4* scoef = (float4*)(smem_raw + SMEM_COEF);
        float2* sg    = (float2*)(smem_raw + SMEM_G);
        float2* sw    = (float2*)(smem_raw + SMEM_W);
        float cs0 = 0.f, cs1 = 0.f;
        const float* ca = Cn + (2 * c2) * DIMS;
        const float* cb = Cn + (2 * c2 + 1) * DIMS;
        #pragma unroll 8
        for (int d = 0; d < DIMS; ++d) {
            cs0 = fmaf(ca[d], ca[d], cs0);
            cs1 = fmaf(cb[d], cb[d], cs1);
        }
        const float L = 1.4426950408889634f;   // log2(e)
        float s0 = Sg[2 * c2];     s0 = 1.0f / (s0 * s0);
        float s1 = Sg[2 * c2 + 1]; s1 = 1.0f / (s1 * s1);
        float a0 = -0.5f * L * s0, a1 = -0.5f * L * s1;
        scoef[c2] = make_float4(a0, a1, a0 * cs0, a1 * cs1);
        sg[c2]    = make_float2(L * s0, L * s1);
        sw[c2 * 3 + 0] = make_float2(Wp[0 * NC + 2 * c2], Wp[0 * NC + 2 * c2 + 1]);
        sw[c2 * 3 + 1] = make_float2(Wp[1 * NC + 2 * c2], Wp[1 * NC + 2 * c2 + 1]);
        sw[c2 * 3 + 2] = make_float2(Wp[2 * NC + 2 * c2], Wp[2 * NC + 2 * c2 + 1]);
    }
    __syncthreads();

    const int wid = tid >> 5, lane = tid & 31;
    const float bo0 = Bp[0], bo1 = Bp[1], bo2 = Bp[2];

    // CTA b owns rowblocks [b*4096/148, (b+1)*4096/148)  (27 or 28 blocks)
    const int nb_start = (int)(((long long)blockIdx.x * ROWBLKS) / NBLK);
    const int nb_end   = (int)((((long long)blockIdx.x + 1) * ROWBLKS) / NBLK);
    const int n        = nb_end - nb_start;

    // warp w takes tasks w, w+8, w+16, w+24  (3 or 4 of them)
    const int cnt = (n - wid + NWARPS - 1) / NWARPS;   // 3 or 4
    int rows[4];
    #pragma unroll
    for (int i = 0; i < 4; ++i)
        rows[i] = ((nb_start + wid + NWARPS * i) << 5) + lane;

    if (cnt == 4) {
        process_rows<4>(X, O, rows, smem_raw, bo0, bo1, bo2);
    } else {
        process_rows<3>(X, O, rows, smem_raw, bo0, bo1, bo2);
    }
}

extern "C" void kernel_launch(void* const* d_in, const int* in_sizes, int n_in,
                              void* d_out, int out_size)
{
    const float* X = nullptr; const float* Cn = nullptr; const float* Sg = nullptr;
    const float* Wp = nullptr; const float* Bp = nullptr;
    for (int i = 0; i < n_in; ++i) {
        switch (in_sizes[i]) {
            case NROWS * DIMS: X  = (const float*)d_in[i]; break;
            case NC * DIMS:    Cn = (const float*)d_in[i]; break;
            case NC:           Sg = (const float*)d_in[i]; break;
            case 3 * NC:       Wp = (const float*)d_in[i]; break;
            case 3:            Bp = (const float*)d_in[i]; break;
            default: break;
        }
    }
    if (!X || !Cn || !Sg || !Wp || !Bp) {
        X  = (const float*)d_in[0]; Cn = (const float*)d_in[1];
        Sg = (const float*)d_in[2]; Wp = (const float*)d_in[3];
        Bp = (const float*)d_in[4];
    }

    cudaFuncSetAttribute(rbfn_kernel,
                         cudaFuncAttributeMaxDynamicSharedMemorySize, SMEM_BYTES);
    rbfn_kernel<<<NBLK, NTH, SMEM_BYTES>>>(X, Cn, Sg, Wp, Bp, (float*)d_out);
}

// round 7
// speedup vs baseline: 1.3625x; 1.3625x over previous
#include <cuda_runtime.h>
#include <cstdint>

#define NROWS 131072
#define DIMS  32
#define NC    512
#define NC2   256
#define NBLK  148
#define NTH   256
#define NWARP 8
#define NRT   4096     /* row tiles of 32 */
#define NNT   64       /* n-tiles of 8 centers */

typedef unsigned long long u64;
typedef unsigned int       u32;

// smem layout (bytes):
//   [0, 131072)        B fragments u32[2][64][2][32][4]  (hi/lo splits)
//   [131072, 135168)   tab1 float4[256] {a0,a1,b0,b1}
//   [135168, 139264)   tab2 float4[256] {w00,w01,w10,w11}
//   [139264, 141312)   tab3 float2[256] {w20,w21}
//   [141312, 143360)   tmpA float[512]
//   [143360, 145408)   tmpB float[512]
#define SM_B    0
#define SM_TAB1 131072
#define SM_TAB2 135168
#define SM_TAB3 139264
#define SM_TMPA 141312
#define SM_TMPB 143360
#define SMEM_BYTES 145408

#define FMA2(acc, a, b) \
    asm("fma.rn.f32x2 %0, %1, %2, %0;" : "+l"(acc) : "l"(a), "l"(b))
#define ADD2(d, a, b) \
    asm("add.rn.f32x2 %0, %1, %2;" : "=l"(d) : "l"(a), "l"(b))

__device__ __forceinline__ u64 dup2(float v) {
    u64 r; u32 u = __float_as_uint(v);
    asm("mov.b64 %0, {%1, %1};" : "=l"(r) : "r"(u));
    return r;
}
__device__ __forceinline__ u64 pack2(u32 a, u32 b) {
    u64 r; asm("mov.b64 %0, {%1, %2};" : "=l"(r) : "r"(a), "r"(b));
    return r;
}
__device__ __forceinline__ void unpack2(u64 v, u32& a, u32& b) {
    asm("mov.b64 {%0, %1}, %2;" : "=r"(a), "=r"(b) : "l"(v));
}
__device__ __forceinline__ float tf32_rna(float f) {
    u32 r; asm("cvt.rna.tf32.f32 %0, %1;" : "=r"(r) : "f"(f));
    return __uint_as_float(r);
}

// m16n8k8 tf32 mma, D accumulates in place.
__device__ __forceinline__ void mma8(float* d, const u32* a, u32 b0, u32 b1) {
    asm("mma.sync.aligned.m16n8k8.row.col.f32.tf32.tf32.f32 "
        "{%0,%1,%2,%3}, {%4,%5,%6,%7}, {%8,%9}, {%0,%1,%2,%3};"
        : "+f"(d[0]), "+f"(d[1]), "+f"(d[2]), "+f"(d[3])
        : "r"(a[0]), "r"(a[1]), "r"(a[2]), "r"(a[3]), "r"(b0), "r"(b1));
}

__global__ void __launch_bounds__(NTH, 1)
rbfn_kernel(const float* __restrict__ X,    // [N, 32]
            const float* __restrict__ Cn,   // [512, 32]
            const float* __restrict__ Sg,   // [1, 512]
            const float* __restrict__ Wp,   // [3, 512]
            const float* __restrict__ Bp,   // [3]
            float* __restrict__ O)          // [N, 3]
{
    extern __shared__ unsigned char sm[];
    const int tid  = threadIdx.x;
    const int wid  = tid >> 5, lane = tid & 31;
    const int g    = lane >> 2, tg = lane & 3;
    const float L  = 1.4426950408889634f;   // log2(e)

    // ---- B fill: scaled-center tf32 hi/lo splits in mma B-fragment order ----
    {
        float* tmpA = (float*)(sm + SM_TMPA);
        float* tmpB = (float*)(sm + SM_TMPB);
        u32*   bb   = (u32*)(sm + SM_B);
        for (int c = tid; c < NC; c += NTH) {
            const float4* cr = (const float4*)(Cn + c * DIMS);
            float s  = Sg[c];
            float al = 0.5f * L / (s * s);
            float g2 = 2.0f * al;
            float csq = 0.f;
            const int n = c >> 3, gg = c & 7;
            #pragma unroll
            for (int q = 0; q < 8; ++q) {
                float4 v = cr[q];
                float e[4] = { v.x, v.y, v.z, v.w };
                #pragma unroll
                for (int t = 0; t < 4; ++t) {
                    csq = fmaf(e[t], e[t], csq);
                    float gv = g2 * e[t];
                    float hi = tf32_rna(gv);
                    float lo = tf32_rna(gv - hi);
                    const int d   = q * 4 + t;
                    const int k   = d >> 3, r = d & 7;
                    const int tgg = r & 3,  j = r >> 2;
                    const int k2  = k >> 1, qq = (k & 1) * 2 + j;
                    const int li  = 4 * gg + tgg;
                    bb[(((     n) * 2 + k2) * 32 + li) * 4 + qq] = __float_as_uint(hi);
                    bb[(((64 + n) * 2 + k2) * 32 + li) * 4 + qq] = __float_as_uint(lo);
                }
            }
            tmpA[c] = -al;
            tmpB[c] = -al * csq;
        }
        __syncthreads();
        float4* tab1 = (float4*)(sm + SM_TAB1);
        float4* tab2 = (float4*)(sm + SM_TAB2);
        float2* tab3 = (float2*)(sm + SM_TAB3);
        for (int c2 = tid; c2 < NC2; c2 += NTH) {
            tab1[c2] = make_float4(tmpA[2*c2], tmpA[2*c2+1], tmpB[2*c2], tmpB[2*c2+1]);
            tab2[c2] = make_float4(Wp[0*NC + 2*c2], Wp[0*NC + 2*c2+1],
                                   Wp[1*NC + 2*c2], Wp[1*NC + 2*c2+1]);
            tab3[c2] = make_float2(Wp[2*NC + 2*c2], Wp[2*NC + 2*c2+1]);
        }
        __syncthreads();
    }

    const ulonglong2* tab1u = (const ulonglong2*)(sm + SM_TAB1);
    const ulonglong2* tab2u = (const ulonglong2*)(sm + SM_TAB2);
    const u64*        tab3u = (const u64*)(sm + SM_TAB3);
    const uint4*      bfr   = (const uint4*)(sm + SM_B);
    const float bo0 = Bp[0], bo1 = Bp[1], bo2 = Bp[2];

    // CTA row-tile range; warp strides by NWARP
    const int t0 = (int)(((long long)blockIdx.x * NRT) / NBLK);
    const int t1 = (int)((((long long)blockIdx.x + 1) * NRT) / NBLK);

    for (int rt = t0 + wid; rt < t1; rt += NWARP) {
        const int rb = rt << 5;

        // ---- load 32 x-values (rows g+8i, cols tg+4m), split, xsq ----
        float xv[4][8];
        #pragma unroll
        for (int i = 0; i < 4; ++i) {
            const float* xr = X + (size_t)(rb + g + 8 * i) * DIMS + tg;
            #pragma unroll
            for (int m = 0; m < 8; ++m) xv[i][m] = __ldg(xr + 4 * m);
        }
        u64 xsqd[4];
        #pragma unroll
        for (int i = 0; i < 4; ++i) {
            float p = 0.f;
            #pragma unroll
            for (int m = 0; m < 8; ++m) p = fmaf(xv[i][m], xv[i][m], p);
            p += __shfl_xor_sync(0xffffffffu, p, 1);
            p += __shfl_xor_sync(0xffffffffu, p, 2);
            xsqd[i] = dup2(p);
        }
        // A fragments: [tile*16 + k*4 + reg]
        u32 Ah[32], Al[32];
        #pragma unroll
        for (int t2 = 0; t2 < 2; ++t2) {
            #pragma unroll
            for (int k = 0; k < 4; ++k) {
                const int b = t2 * 16 + k * 4;
                float v0 = xv[2*t2  ][2*k],   v1 = xv[2*t2+1][2*k];
                float v2 = xv[2*t2  ][2*k+1], v3 = xv[2*t2+1][2*k+1];
                float h;
                h = tf32_rna(v0); Ah[b+0] = __float_as_uint(h);
                Al[b+0] = __float_as_uint(tf32_rna(v0 - h));
                h = tf32_rna(v1); Ah[b+1] = __float_as_uint(h);
                Al[b+1] = __float_as_uint(tf32_rna(v1 - h));
                h = tf32_rna(v2); Ah[b+2] = __float_as_uint(h);
                Al[b+2] = __float_as_uint(tf32_rna(v2 - h));
                h = tf32_rna(v3); Ah[b+3] = __float_as_uint(h);
                Al[b+3] = __float_as_uint(tf32_rna(v3 - h));
            }
        }

        u64 op0[4], op1[4], op2[4];
        #pragma unroll
        for (int sl = 0; sl < 4; ++sl) { op0[sl] = 0; op1[sl] = 0; op2[sl] = 0; }

        #pragma unroll 1
        for (int n = 0; n < NNT; ++n) {
            uint4 h01 = bfr[((     n) * 2 + 0) * 32 + lane];
            uint4 h23 = bfr[((     n) * 2 + 1) * 32 + lane];
            uint4 l01 = bfr[((64 + n) * 2 + 0) * 32 + lane];
            uint4 l23 = bfr[((64 + n) * 2 + 1) * 32 + lane];
            float d0[4] = {0.f,0.f,0.f,0.f}, d1[4] = {0.f,0.f,0.f,0.f};
            // k0
            mma8(d0, Ah+ 0, h01.x, h01.y); mma8(d1, Ah+16, h01.x, h01.y);
            mma8(d0, Al+ 0, h01.x, h01.y); mma8(d1, Al+16, h01.x, h01.y);
            mma8(d0, Ah+ 0, l01.x, l01.y); mma8(d1, Ah+16, l01.x, l01.y);
            // k1
            mma8(d0, Ah+ 4, h01.z, h01.w); mma8(d1, Ah+20, h01.z, h01.w);
            mma8(d0, Al+ 4, h01.z, h01.w); mma8(d1, Al+20, h01.z, h01.w);
            mma8(d0, Ah+ 4, l01.z, l01.w); mma8(d1, Ah+20, l01.z, l01.w);
            // k2
            mma8(d0, Ah+ 8, h23.x, h23.y); mma8(d1, Ah+24, h23.x, h23.y);
            mma8(d0, Al+ 8, h23.x, h23.y); mma8(d1, Al+24, h23.x, h23.y);
            mma8(d0, Ah+ 8, l23.x, l23.y); mma8(d1, Ah+24, l23.x, l23.y);
            // k3
            mma8(d0, Ah+12, h23.z, h23.w); mma8(d1, Ah+28, h23.z, h23.w);
            mma8(d0, Al+12, h23.z, h23.w); mma8(d1, Al+28, h23.z, h23.w);
            mma8(d0, Ah+12, l23.z, l23.w); mma8(d1, Ah+28, l23.z, l23.w);

            // ---- epilogue on this n-tile (cols 8n+2tg, 8n+2tg+1) ----
            const int c2 = n * 4 + tg;
            const ulonglong2 ab  = tab1u[c2];
            const ulonglong2 w01 = tab2u[c2];
            const u64        w2v = tab3u[c2];
            #pragma unroll
            for (int sl = 0; sl < 4; ++sl) {
                float p0 = (sl & 1) ? ((sl >> 1) ? d1[2] : d0[2])
                                    : ((sl >> 1) ? d1[0] : d0[0]);
                float p1 = (sl & 1) ? ((sl >> 1) ? d1[3] : d0[3])
                                    : ((sl >> 1) ? d1[1] : d0[1]);
                u64 dp = pack2(__float_as_uint(p0), __float_as_uint(p1));
                u64 tt;
                asm("fma.rn.f32x2 %0, %1, %2, %3;" : "=l"(tt)
                    : "l"(ab.x), "l"(xsqd[sl]), "l"(ab.y));
                ADD2(tt, tt, dp);                     // t/2
                u32 ta, tb; unpack2(tt, ta, tb);
                float e0, e1;
                asm("ex2.approx.ftz.f32 %0, %1;" : "=f"(e0) : "f"(__uint_as_float(ta)));
                asm("ex2.approx.ftz.f32 %0, %1;" : "=f"(e1) : "f"(__uint_as_float(tb)));
                u64 rp = pack2(__float_as_uint(e0), __float_as_uint(e1)), h;
                asm("mul.rn.f32x2 %0, %1, %2;" : "=l"(h) : "l"(rp), "l"(rp));
                FMA2(op0[sl], h, w01.x);
                FMA2(op1[sl], h, w01.y);
                FMA2(op2[sl], h, w2v);
            }
        }

        // ---- reduce over the 4 tg-lanes, store ----
        #pragma unroll
        for (int sl = 0; sl < 4; ++sl) {
            u32 a_, b_;
            float o0, o1, o2;
            unpack2(op0[sl], a_, b_); o0 = __uint_as_float(a_) + __uint_as_float(b_);
            unpack2(op1[sl], a_, b_); o1 = __uint_as_float(a_) + __uint_as_float(b_);
            unpack2(op2[sl], a_, b_); o2 = __uint_as_float(a_) + __uint_as_float(b_);
            o0 += __shfl_xor_sync(0xffffffffu, o0, 1);
            o0 += __shfl_xor_sync(0xffffffffu, o0, 2);
            o1 += __shfl_xor_sync(0xffffffffu, o1, 1);
            o1 += __shfl_xor_sync(0xffffffffu, o1, 2);
            o2 += __shfl_xor_sync(0xffffffffu, o2, 1);
            o2 += __shfl_xor_sync(0xffffffffu, o2, 2);
            if (tg == 0) {
                float* Or = O + (size_t)(rb + g + 8 * sl) * 3;
                Or[0] = o0 + bo0;
                Or[1] = o1 + bo1;
                Or[2] = o2 + bo2;
            }
        }
    }
}

extern "C" void kernel_launch(void* const* d_in, const int* in_sizes, int n_in,
                              void* d_out, int out_size)
{
    const float* X = nullptr; const float* Cn = nullptr; const float* Sg = nullptr;
    const float* Wp = nullptr; const float* Bp = nullptr;
    for (int i = 0; i < n_in; ++i) {
        switch (in_sizes[i]) {
            case NROWS * DIMS: X  = (const float*)d_in[i]; break;
            case NC * DIMS:    Cn = (const float*)d_in[i]; break;
            case NC:           Sg = (const float*)d_in[i]; break;
            case 3 * NC:       Wp = (const float*)d_in[i]; break;
            case 3:            Bp = (const float*)d_in[i]; break;
            default: break;
        }
    }
    if (!X || !Cn || !Sg || !Wp || !Bp) {
        X  = (const float*)d_in[0]; Cn = (const float*)d_in[1];
        Sg = (const float*)d_in[2]; Wp = (const float*)d_in[3];
        Bp = (const float*)d_in[4];
    }

    cudaFuncSetAttribute(rbfn_kernel,
                         cudaFuncAttributeMaxDynamicSharedMemorySize, SMEM_BYTES);
    rbfn_kernel<<<NBLK, NTH, SMEM_BYTES>>>(X, Cn, Sg, Wp, Bp, (float*)d_out);
}